// round 14
// baseline (speedup 1.0000x reference)
#include <cuda_runtime.h>
#include <cuda_bf16.h>
#include <cstdint>

#define BB 4096
#define TT 16
#define HH 768
#define AA 128
#define VV 16
#define LL 2
#define MTILE 64
#define MAXT 80
#define NSPL 4
#define NUNITS (NSPL * MAXT)
#define KSPL 192
#define NCHK 3             // 192 / 64
#define KCH 64
#define STRB 144           // bytes per smem row: 64 bf16 + 16B pad
#define SA_B (64 * STRB)           // 9216
#define STAGEB (SA_B + 128 * STRB) // 27648
#define DYN_SMEM (NCHK * STAGEB)   // 82944 — all of this split's K resident, 2 CTA/SM

// fused-prep grid partition
#define NPREPX 512                  // 8 rows per block
#define NWDT   (VV * (HH / 32))     // 384
#define NFOLD  (VV * 16)            // 256
#define NBIN   VV                   // 16
#define NPREP  (NPREPX + NWDT + NFOLD + NBIN + 1)   // +1 sem-zero block

// ---------------- device scratch ----------------
__device__ int g_counts[VV];
__device__ int g_bins[VV * BB];
__device__ float g_Wc2[VV * AA * LL];
__device__ float g_buc[VV * LL];
__device__ float g_xc[BB * LL];
__device__ int g_sem[MAXT];
__device__ float g_part[NUNITS * MTILE * AA];
__device__ __align__(16) __nv_bfloat16 g_xbf16[BB * HH];
__device__ __align__(16) __nv_bfloat16 g_WdT[VV * AA * HH];

// ---------------- PTX helpers (sm_80+ baseline only) ----------------
__device__ __forceinline__ uint32_t smem_to_u32(const void* p) {
    uint32_t a;
    asm("{ .reg .u64 t; cvta.to.shared.u64 t, %1; cvt.u32.u64 %0, t; }"
        : "=r"(a) : "l"(p));
    return a;
}
#define CP_ASYNC16(dst, src) \
    asm volatile("cp.async.cg.shared.global [%0], [%1], 16;" :: "r"(dst), "l"(src) : "memory")
#define CP_COMMIT() asm volatile("cp.async.commit_group;" ::: "memory")
#define CP_WAITN(n) asm volatile("cp.async.wait_group %0;" :: "n"(n) : "memory")

__device__ __forceinline__ void ldsm4(uint32_t* r, uint32_t addr) {
    asm volatile("ldmatrix.sync.aligned.m8n8.x4.shared.b16 {%0,%1,%2,%3}, [%4];"
        : "=r"(r[0]), "=r"(r[1]), "=r"(r[2]), "=r"(r[3]) : "r"(addr));
}
__device__ __forceinline__ void mma16816(float* c, const uint32_t* a, const uint32_t* b) {
    asm volatile(
        "mma.sync.aligned.m16n8k16.row.col.f32.bf16.bf16.f32 "
        "{%0,%1,%2,%3}, {%4,%5,%6,%7}, {%8,%9}, {%0,%1,%2,%3};"
        : "+f"(c[0]), "+f"(c[1]), "+f"(c[2]), "+f"(c[3])
        : "r"(a[0]), "r"(a[1]), "r"(a[2]), "r"(a[3]), "r"(b[0]), "r"(b[1]));
}
__device__ __forceinline__ float gelu_fast(float x) {
    float x3 = x * x * x;
    float arg = 0.7978845608028654f * (x + 0.044715f * x3);
    float t;
    asm("tanh.approx.f32 %0, %1;" : "=f"(t) : "f"(arg));
    return 0.5f * x * (1.0f + t);
}

// ---------------- fused prep kernel ----------------
__global__ void __launch_bounds__(256, 4)
va_prep(const float* __restrict__ lh, const float* __restrict__ Wc,
        const float* __restrict__ Wd, const float* __restrict__ Wu,
        const float* __restrict__ bu, const int* __restrict__ vids) {
    __shared__ __align__(16) char sbuf[32 * 130 * 2];
    const int bid  = blockIdx.x;
    const int tid  = threadIdx.x;
    const int warp = tid >> 5;
    const int lane = tid & 31;

    if (bid < NPREPX) {
        float* sWc = (float*)sbuf;
        for (int i = tid; i < HH * LL; i += 256) sWc[i] = Wc[i];
        __syncthreads();

        const int r = bid * 8 + warp;
        const float* src = lh + (size_t)r * TT * HH;
        float s0 = 0.f, s1 = 0.f;
        #pragma unroll
        for (int it = 0; it < 6; it++) {
            int h = it * 128 + lane * 4;
            float4 w = *(const float4*)(src + h);
            s0 = fmaf(w.x, sWc[h + 0], s0);
            s0 = fmaf(w.y, sWc[h + 1], s0);
            s0 = fmaf(w.z, sWc[h + 2], s0);
            s0 = fmaf(w.w, sWc[h + 3], s0);
            s1 = fmaf(w.x, sWc[HH + h + 0], s1);
            s1 = fmaf(w.y, sWc[HH + h + 1], s1);
            s1 = fmaf(w.z, sWc[HH + h + 2], s1);
            s1 = fmaf(w.w, sWc[HH + h + 3], s1);
            __nv_bfloat162 p0 = __floats2bfloat162_rn(w.x, w.y);
            __nv_bfloat162 p1 = __floats2bfloat162_rn(w.z, w.w);
            uint2 pk;
            pk.x = *reinterpret_cast<uint32_t*>(&p0);
            pk.y = *reinterpret_cast<uint32_t*>(&p1);
            *reinterpret_cast<uint2*>(g_xbf16 + (size_t)r * HH + h) = pk;
        }
        #pragma unroll
        for (int off = 16; off; off >>= 1) {
            s0 += __shfl_xor_sync(0xFFFFFFFFu, s0, off);
            s1 += __shfl_xor_sync(0xFFFFFFFFu, s1, off);
        }
        if (lane == 0) {
            g_xc[r * 2 + 0] = s0;
            g_xc[r * 2 + 1] = s1;
        }
    } else if (bid < NPREPX + NWDT) {
        __nv_bfloat16* s = (__nv_bfloat16*)sbuf;
        const int idx = bid - NPREPX;
        const int v   = idx / (HH / 32);
        const int k0  = (idx % (HH / 32)) * 32;

        const float* base = Wd + (size_t)v * HH * AA + (size_t)k0 * AA;
        #pragma unroll
        for (int i = 0; i < 4; i++) {
            int idx4 = tid + i * 256;
            int k  = idx4 >> 5;
            int n4 = (idx4 & 31) * 4;
            float4 w = *(const float4*)(base + k * AA + n4);
            __nv_bfloat162 p0 = __floats2bfloat162_rn(w.x, w.y);
            __nv_bfloat162 p1 = __floats2bfloat162_rn(w.z, w.w);
            *reinterpret_cast<__nv_bfloat162*>(&s[k * 130 + n4])     = p0;
            *reinterpret_cast<__nv_bfloat162*>(&s[k * 130 + n4 + 2]) = p1;
        }
        __syncthreads();

        const int n     = tid >> 1;
        const int khalf = (tid & 1) * 16;
        __nv_bfloat16 tmp[16];
        #pragma unroll
        for (int e = 0; e < 16; e++)
            tmp[e] = s[(khalf + e) * 130 + n];
        uint4* dst = reinterpret_cast<uint4*>(g_WdT + ((size_t)v * AA + n) * HH + k0 + khalf);
        dst[0] = *reinterpret_cast<uint4*>(tmp);
        dst[1] = *reinterpret_cast<uint4*>(tmp + 8);
    } else if (bid < NPREPX + NWDT + NFOLD) {
        float* sWc = (float*)sbuf;
        const int idx = bid - (NPREPX + NWDT);
        const int v   = idx >> 4;
        const int seg = idx & 15;

        for (int i = tid; i < HH * LL; i += 256) sWc[i] = Wc[i];
        __syncthreads();

        const int a = seg * 8 + warp;
        const float* row = Wu + ((size_t)v * AA + a) * HH;
        float s0 = 0.f, s1 = 0.f;
        #pragma unroll
        for (int it = 0; it < 6; it++) {
            int h = it * 128 + lane * 4;
            float4 w = *(const float4*)(row + h);
            s0 = fmaf(w.x, sWc[h + 0], s0);
            s0 = fmaf(w.y, sWc[h + 1], s0);
            s0 = fmaf(w.z, sWc[h + 2], s0);
            s0 = fmaf(w.w, sWc[h + 3], s0);
            s1 = fmaf(w.x, sWc[HH + h + 0], s1);
            s1 = fmaf(w.y, sWc[HH + h + 1], s1);
            s1 = fmaf(w.z, sWc[HH + h + 2], s1);
            s1 = fmaf(w.w, sWc[HH + h + 3], s1);
        }
        #pragma unroll
        for (int off = 16; off; off >>= 1) {
            s0 += __shfl_xor_sync(0xFFFFFFFFu, s0, off);
            s1 += __shfl_xor_sync(0xFFFFFFFFu, s1, off);
        }
        if (lane == 0) {
            g_Wc2[(v * AA + a) * 2 + 0] = s0;
            g_Wc2[(v * AA + a) * 2 + 1] = s1;
        }
        if (seg == 0 && warp == 0) {
            const float* brow = bu + (size_t)v * HH;
            float t0 = 0.f, t1 = 0.f;
            #pragma unroll
            for (int it = 0; it < 6; it++) {
                int h = it * 128 + lane * 4;
                float4 w = *(const float4*)(brow + h);
                t0 = fmaf(w.x, sWc[h + 0], t0);
                t0 = fmaf(w.y, sWc[h + 1], t0);
                t0 = fmaf(w.z, sWc[h + 2], t0);
                t0 = fmaf(w.w, sWc[h + 3], t0);
                t1 = fmaf(w.x, sWc[HH + h + 0], t1);
                t1 = fmaf(w.y, sWc[HH + h + 1], t1);
                t1 = fmaf(w.z, sWc[HH + h + 2], t1);
                t1 = fmaf(w.w, sWc[HH + h + 3], t1);
            }
            #pragma unroll
            for (int off = 16; off; off >>= 1) {
                t0 += __shfl_xor_sync(0xFFFFFFFFu, t0, off);
                t1 += __shfl_xor_sync(0xFFFFFFFFu, t1, off);
            }
            if (lane == 0) {
                g_buc[v * 2 + 0] = t0;
                g_buc[v * 2 + 1] = t1;
            }
        }
    } else if (bid < NPREPX + NWDT + NFOLD + NBIN) {
        int* scnt = (int*)sbuf;
        const int v = bid - (NPREPX + NWDT + NFOLD);
        if (tid == 0) *scnt = 0;
        __syncthreads();
        for (int i = tid; i < BB; i += 256) {
            if (vids[i] == v) {
                int s = atomicAdd(scnt, 1);
                g_bins[v * BB + s] = i;
            }
        }
        __syncthreads();
        if (tid == 0) g_counts[v] = *scnt;
    } else {
        if (tid < MAXT) g_sem[tid] = 0;
    }
}

// ---------------- main mma.sync kernel: full-K prefetch, split-K=4 ----------------
extern "C" __global__ void __launch_bounds__(256, 2)
va_main_mma(const float* __restrict__ bd, const float* __restrict__ bc,
            float* __restrict__ out) {
    extern __shared__ char dsm[];
    __shared__ int   sB[MTILE];
    __shared__ float sBd[128];
    __shared__ float sWc2[256];
    __shared__ int   sLast;

    const int tid  = threadIdx.x;
    const int warp = tid >> 5;
    const int lane = tid & 31;
    const int wm   = warp & 1;    // row group: 32*wm
    const int wn   = warp >> 1;   // col group: 32*wn

    const int t  = blockIdx.x >> 2;   // tile
    const int ks = blockIdx.x & 3;    // K split

    int vv = -1, seg = 0, cnt = 0;
    {
        int nt = 0;
        #pragma unroll
        for (int vi = 0; vi < VV; vi++) {
            int c  = g_counts[vi];
            int tv = (c + MTILE - 1) >> 6;
            if (vv < 0 && t >= nt && t < nt + tv) { vv = vi; seg = t - nt; cnt = c; }
            nt += tv;
        }
    }
    if (vv < 0) return;
    const int row0 = seg * MTILE;

    if (tid < MTILE) {
        int gr = row0 + tid;
        sB[tid] = (gr < cnt) ? g_bins[vv * BB + gr] : -1;
    }
    if (tid < 128) sBd[tid] = bd[vv * AA + tid];
    sWc2[tid] = g_Wc2[vv * AA * LL + tid];
    __syncthreads();

    const uint32_t dynb = smem_to_u32(dsm);
    const int ksb = ks * KSPL;

    // per-thread cp.async: 6 16B loads per chunk (A: 512 loads, B: 1024)
    const __nv_bfloat16* src6[6];
    uint32_t dst6[6];
    #pragma unroll
    for (int i = 0; i < 6; i++) {
        int idx = tid + i * 256;
        if (idx < 512) {
            int row = idx >> 3, sg = idx & 7;
            int brow = sB[row];
            if (brow < 0) brow = 0;
            src6[i] = g_xbf16 + (size_t)brow * HH + ksb + sg * 8;
            dst6[i] = (uint32_t)(row * STRB + sg * 16);
        } else {
            int j = idx - 512;
            int row = j >> 3, sg = j & 7;
            src6[i] = g_WdT + ((size_t)vv * AA + row) * HH + ksb + sg * 8;
            dst6[i] = (uint32_t)(SA_B + row * STRB + sg * 16);
        }
    }

    // ---- prefetch ALL 3 chunks (48 KB) immediately ----
    #pragma unroll
    for (int c = 0; c < NCHK; c++) {
        uint32_t base = dynb + c * STAGEB;
        #pragma unroll
        for (int i = 0; i < 6; i++)
            CP_ASYNC16(base + dst6[i], src6[i] + c * KCH);
        CP_COMMIT();
    }

    uint32_t aOff[2], bOff[2];
    #pragma unroll
    for (int mf = 0; mf < 2; mf++)
        aOff[mf] = (uint32_t)((32 * wm + 16 * mf + ((lane >> 3) & 1) * 8 + (lane & 7)) * STRB
                              + (lane >> 4) * 16);
    #pragma unroll
    for (int p = 0; p < 2; p++)
        bOff[p] = (uint32_t)(SA_B
                              + (32 * wn + 16 * p + (lane >> 4) * 8 + (lane & 7)) * STRB
                              + ((lane >> 3) & 1) * 16);

    float acc[2][4][4];
    #pragma unroll
    for (int mf = 0; mf < 2; mf++)
        #pragma unroll
        for (int nf = 0; nf < 4; nf++)
            #pragma unroll
            for (int e = 0; e < 4; e++) acc[mf][nf][e] = 0.f;

    // ---- compute: progressive waits, no buffer reuse ----
    #pragma unroll
    for (int c = 0; c < NCHK; c++) {
        switch (c) {
            case 0: CP_WAITN(2); break;
            case 1: CP_WAITN(1); break;
            default: CP_WAITN(0); break;
        }
        __syncthreads();

        const uint32_t base = dynb + c * STAGEB;
        #pragma unroll
        for (int step = 0; step < 4; step++) {
            const uint32_t kb = step * 32;
            uint32_t af[2][4], bf[2][4];
            ldsm4(af[0], base + aOff[0] + kb);
            ldsm4(af[1], base + aOff[1] + kb);
            ldsm4(bf[0], base + bOff[0] + kb);
            ldsm4(bf[1], base + bOff[1] + kb);
            #pragma unroll
            for (int mf = 0; mf < 2; mf++)
                #pragma unroll
                for (int p = 0; p < 2; p++) {
                    mma16816(acc[mf][2 * p + 0], af[mf], &bf[p][0]);
                    mma16816(acc[mf][2 * p + 1], af[mf], &bf[p][2]);
                }
        }
    }

    // ---- store split-K partial ----
    float* part = g_part + (size_t)blockIdx.x * (MTILE * AA);
    #pragma unroll
    for (int mf = 0; mf < 2; mf++)
        #pragma unroll
        for (int nf = 0; nf < 4; nf++)
            #pragma unroll
            for (int hh = 0; hh < 2; hh++) {
                int row  = 32 * wm + 16 * mf + 8 * hh + (lane >> 2);
                int col0 = 32 * wn + 8 * nf + 2 * (lane & 3);
                *(float2*)(part + row * AA + col0) =
                    make_float2(acc[mf][nf][2 * hh], acc[mf][nf][2 * hh + 1]);
            }
    __syncthreads();
    if (tid == 0) {
        __threadfence();
        int old = atomicAdd(&g_sem[t], 1);
        sLast = (old == NSPL - 1);
    }
    __syncthreads();
    if (!sLast) return;

    // ---- last finisher: sum 4 partials (fixed order), gelu + head ----
    const float* p0 = g_part + (size_t)(t * NSPL) * (MTILE * AA);
    const int row = tid >> 2;
    const int q   = tid & 3;
    const int b   = sB[row];
    float a0 = 0.f, a1 = 0.f;
    #pragma unroll
    for (int cc = 0; cc < 8; cc++) {
        int col = q * 32 + cc * 4;
        float4 x0 = *(const float4*)(p0 + row * AA + col);
        float4 x1 = *(const float4*)(p0 + 1 * MTILE * AA + row * AA + col);
        float4 x2 = *(const float4*)(p0 + 2 * MTILE * AA + row * AA + col);
        float4 x3 = *(const float4*)(p0 + 3 * MTILE * AA + row * AA + col);
        float u0 = ((x0.x + x1.x) + (x2.x + x3.x)) + sBd[col + 0];
        float u1 = ((x0.y + x1.y) + (x2.y + x3.y)) + sBd[col + 1];
        float u2 = ((x0.z + x1.z) + (x2.z + x3.z)) + sBd[col + 2];
        float u3 = ((x0.w + x1.w) + (x2.w + x3.w)) + sBd[col + 3];
        float h0 = gelu_fast(u0);
        float h1 = gelu_fast(u1);
        float h2 = gelu_fast(u2);
        float h3 = gelu_fast(u3);
        a0 = fmaf(h0, sWc2[(col + 0) * 2 + 0], a0);
        a1 = fmaf(h0, sWc2[(col + 0) * 2 + 1], a1);
        a0 = fmaf(h1, sWc2[(col + 1) * 2 + 0], a0);
        a1 = fmaf(h1, sWc2[(col + 1) * 2 + 1], a1);
        a0 = fmaf(h2, sWc2[(col + 2) * 2 + 0], a0);
        a1 = fmaf(h2, sWc2[(col + 2) * 2 + 1], a1);
        a0 = fmaf(h3, sWc2[(col + 3) * 2 + 0], a0);
        a1 = fmaf(h3, sWc2[(col + 3) * 2 + 1], a1);
    }
    a0 += __shfl_xor_sync(0xFFFFFFFFu, a0, 1);
    a0 += __shfl_xor_sync(0xFFFFFFFFu, a0, 2);
    a1 += __shfl_xor_sync(0xFFFFFFFFu, a1, 1);
    a1 += __shfl_xor_sync(0xFFFFFFFFu, a1, 2);
    if (q == 0 && b >= 0) {
        out[b * 2 + 0] = g_xc[b * 2 + 0] + a0 + g_buc[vv * 2 + 0] + __ldg(bc + 0);
        out[b * 2 + 1] = g_xc[b * 2 + 1] + a1 + g_buc[vv * 2 + 1] + __ldg(bc + 1);
    }
}

extern "C" void kernel_launch(void* const* d_in, const int* in_sizes, int n_in,
                              void* d_out, int out_size) {
    const float* lh   = (const float*)d_in[0];
    const int*   vids = (const int*)d_in[2];
    const float* Wd   = (const float*)d_in[3];
    const float* bd   = (const float*)d_in[4];
    const float* Wu   = (const float*)d_in[5];
    const float* bu   = (const float*)d_in[6];
    const float* Wc   = (const float*)d_in[7];
    const float* bc   = (const float*)d_in[8];
    float* out = (float*)d_out;

    cudaFuncSetAttribute(va_main_mma, cudaFuncAttributeMaxDynamicSharedMemorySize, DYN_SMEM);

    va_prep<<<NPREP, 256>>>(lh, Wc, Wd, Wu, bu, vids);
    va_main_mma<<<NUNITS, 256, DYN_SMEM>>>(bd, bc, out);
}

// round 16
// speedup vs baseline: 1.5355x; 1.5355x over previous
#include <cuda_runtime.h>
#include <cuda_bf16.h>
#include <cstdint>

#define BB 4096
#define TT 16
#define HH 768
#define AA 128
#define VV 16
#define LL 2
#define MTILE 32
#define NTILES_MAX 144
#define NCHK 6             // 768 / 128
#define KCH 128
#define STR2 272           // bytes per smem row: 128 bf16 (256B) + 16B pad
#define SA2 (MTILE * STR2)           // 8704
#define STAGE2 (SA2 + 128 * STR2)    // 43520
#define DYN_SMEM (3 * STAGE2)        // 130560 — 3-stage ring

// fused-prep grid partition
#define NPREPX 512                  // 8 rows per block
#define NWDT   (VV * (HH / 32))     // 384
#define NFOLD  (VV * 16)            // 256
#define NBIN   VV                   // 16
#define NPREP  (NPREPX + NWDT + NFOLD + NBIN)

// ---------------- device scratch ----------------
__device__ int g_counts[VV];
__device__ int g_bins[VV * BB];
__device__ float g_Wc2[VV * AA * LL];
__device__ float g_buc[VV * LL];
__device__ float g_xc[BB * LL];
__device__ __align__(16) __nv_bfloat16 g_xbf16[BB * HH];
__device__ __align__(16) __nv_bfloat16 g_WdT[VV * AA * HH];

// ---------------- PTX helpers (sm_80+ baseline only) ----------------
__device__ __forceinline__ uint32_t smem_to_u32(const void* p) {
    uint32_t a;
    asm("{ .reg .u64 t; cvta.to.shared.u64 t, %1; cvt.u32.u64 %0, t; }"
        : "=r"(a) : "l"(p));
    return a;
}
#define CP_ASYNC16(dst, src) \
    asm volatile("cp.async.cg.shared.global [%0], [%1], 16;" :: "r"(dst), "l"(src) : "memory")
#define CP_COMMIT() asm volatile("cp.async.commit_group;" ::: "memory")
#define CP_WAITN(n) asm volatile("cp.async.wait_group %0;" :: "n"(n) : "memory")

__device__ __forceinline__ void ldsm4(uint32_t* r, uint32_t addr) {
    asm volatile("ldmatrix.sync.aligned.m8n8.x4.shared.b16 {%0,%1,%2,%3}, [%4];"
        : "=r"(r[0]), "=r"(r[1]), "=r"(r[2]), "=r"(r[3]) : "r"(addr));
}
__device__ __forceinline__ void mma16816(float* c, const uint32_t* a, const uint32_t* b) {
    asm volatile(
        "mma.sync.aligned.m16n8k16.row.col.f32.bf16.bf16.f32 "
        "{%0,%1,%2,%3}, {%4,%5,%6,%7}, {%8,%9}, {%0,%1,%2,%3};"
        : "+f"(c[0]), "+f"(c[1]), "+f"(c[2]), "+f"(c[3])
        : "r"(a[0]), "r"(a[1]), "r"(a[2]), "r"(a[3]), "r"(b[0]), "r"(b[1]));
}
__device__ __forceinline__ float gelu_fast(float x) {
    float x3 = x * x * x;
    float arg = 0.7978845608028654f * (x + 0.044715f * x3);
    float t;
    asm("tanh.approx.f32 %0, %1;" : "=f"(t) : "f"(arg));
    return 0.5f * x * (1.0f + t);
}

// ---------------- fused prep kernel ----------------
__global__ void __launch_bounds__(256, 4)
va_prep(const float* __restrict__ lh, const float* __restrict__ Wc,
        const float* __restrict__ Wd, const float* __restrict__ Wu,
        const float* __restrict__ bu, const int* __restrict__ vids) {
    __shared__ __align__(16) char sbuf[32 * 130 * 2];
    const int bid  = blockIdx.x;
    const int tid  = threadIdx.x;
    const int warp = tid >> 5;
    const int lane = tid & 31;

    if (bid < NPREPX) {
        float* sWc = (float*)sbuf;
        for (int i = tid; i < HH * LL; i += 256) sWc[i] = Wc[i];
        __syncthreads();

        const int r = bid * 8 + warp;
        const float* src = lh + (size_t)r * TT * HH;
        float s0 = 0.f, s1 = 0.f;
        #pragma unroll
        for (int it = 0; it < 6; it++) {
            int h = it * 128 + lane * 4;
            float4 w = *(const float4*)(src + h);
            s0 = fmaf(w.x, sWc[h + 0], s0);
            s0 = fmaf(w.y, sWc[h + 1], s0);
            s0 = fmaf(w.z, sWc[h + 2], s0);
            s0 = fmaf(w.w, sWc[h + 3], s0);
            s1 = fmaf(w.x, sWc[HH + h + 0], s1);
            s1 = fmaf(w.y, sWc[HH + h + 1], s1);
            s1 = fmaf(w.z, sWc[HH + h + 2], s1);
            s1 = fmaf(w.w, sWc[HH + h + 3], s1);
            __nv_bfloat162 p0 = __floats2bfloat162_rn(w.x, w.y);
            __nv_bfloat162 p1 = __floats2bfloat162_rn(w.z, w.w);
            uint2 pk;
            pk.x = *reinterpret_cast<uint32_t*>(&p0);
            pk.y = *reinterpret_cast<uint32_t*>(&p1);
            *reinterpret_cast<uint2*>(g_xbf16 + (size_t)r * HH + h) = pk;
        }
        #pragma unroll
        for (int off = 16; off; off >>= 1) {
            s0 += __shfl_xor_sync(0xFFFFFFFFu, s0, off);
            s1 += __shfl_xor_sync(0xFFFFFFFFu, s1, off);
        }
        if (lane == 0) {
            g_xc[r * 2 + 0] = s0;
            g_xc[r * 2 + 1] = s1;
        }
    } else if (bid < NPREPX + NWDT) {
        __nv_bfloat16* s = (__nv_bfloat16*)sbuf;
        const int idx = bid - NPREPX;
        const int v   = idx / (HH / 32);
        const int k0  = (idx % (HH / 32)) * 32;

        const float* base = Wd + (size_t)v * HH * AA + (size_t)k0 * AA;
        #pragma unroll
        for (int i = 0; i < 4; i++) {
            int idx4 = tid + i * 256;
            int k  = idx4 >> 5;
            int n4 = (idx4 & 31) * 4;
            float4 w = *(const float4*)(base + k * AA + n4);
            __nv_bfloat162 p0 = __floats2bfloat162_rn(w.x, w.y);
            __nv_bfloat162 p1 = __floats2bfloat162_rn(w.z, w.w);
            *reinterpret_cast<__nv_bfloat162*>(&s[k * 130 + n4])     = p0;
            *reinterpret_cast<__nv_bfloat162*>(&s[k * 130 + n4 + 2]) = p1;
        }
        __syncthreads();

        const int n     = tid >> 1;
        const int khalf = (tid & 1) * 16;
        __nv_bfloat16 tmp[16];
        #pragma unroll
        for (int e = 0; e < 16; e++)
            tmp[e] = s[(khalf + e) * 130 + n];
        uint4* dst = reinterpret_cast<uint4*>(g_WdT + ((size_t)v * AA + n) * HH + k0 + khalf);
        dst[0] = *reinterpret_cast<uint4*>(tmp);
        dst[1] = *reinterpret_cast<uint4*>(tmp + 8);
    } else if (bid < NPREPX + NWDT + NFOLD) {
        float* sWc = (float*)sbuf;
        const int idx = bid - (NPREPX + NWDT);
        const int v   = idx >> 4;
        const int seg = idx & 15;

        for (int i = tid; i < HH * LL; i += 256) sWc[i] = Wc[i];
        __syncthreads();

        const int a = seg * 8 + warp;
        const float* row = Wu + ((size_t)v * AA + a) * HH;
        float s0 = 0.f, s1 = 0.f;
        #pragma unroll
        for (int it = 0; it < 6; it++) {
            int h = it * 128 + lane * 4;
            float4 w = *(const float4*)(row + h);
            s0 = fmaf(w.x, sWc[h + 0], s0);
            s0 = fmaf(w.y, sWc[h + 1], s0);
            s0 = fmaf(w.z, sWc[h + 2], s0);
            s0 = fmaf(w.w, sWc[h + 3], s0);
            s1 = fmaf(w.x, sWc[HH + h + 0], s1);
            s1 = fmaf(w.y, sWc[HH + h + 1], s1);
            s1 = fmaf(w.z, sWc[HH + h + 2], s1);
            s1 = fmaf(w.w, sWc[HH + h + 3], s1);
        }
        #pragma unroll
        for (int off = 16; off; off >>= 1) {
            s0 += __shfl_xor_sync(0xFFFFFFFFu, s0, off);
            s1 += __shfl_xor_sync(0xFFFFFFFFu, s1, off);
        }
        if (lane == 0) {
            g_Wc2[(v * AA + a) * 2 + 0] = s0;
            g_Wc2[(v * AA + a) * 2 + 1] = s1;
        }
        if (seg == 0 && warp == 0) {
            const float* brow = bu + (size_t)v * HH;
            float t0 = 0.f, t1 = 0.f;
            #pragma unroll
            for (int it = 0; it < 6; it++) {
                int h = it * 128 + lane * 4;
                float4 w = *(const float4*)(brow + h);
                t0 = fmaf(w.x, sWc[h + 0], t0);
                t0 = fmaf(w.y, sWc[h + 1], t0);
                t0 = fmaf(w.z, sWc[h + 2], t0);
                t0 = fmaf(w.w, sWc[h + 3], t0);
                t1 = fmaf(w.x, sWc[HH + h + 0], t1);
                t1 = fmaf(w.y, sWc[HH + h + 1], t1);
                t1 = fmaf(w.z, sWc[HH + h + 2], t1);
                t1 = fmaf(w.w, sWc[HH + h + 3], t1);
            }
            #pragma unroll
            for (int off = 16; off; off >>= 1) {
                t0 += __shfl_xor_sync(0xFFFFFFFFu, t0, off);
                t1 += __shfl_xor_sync(0xFFFFFFFFu, t1, off);
            }
            if (lane == 0) {
                g_buc[v * 2 + 0] = t0;
                g_buc[v * 2 + 1] = t1;
            }
        }
    } else {
        int* scnt = (int*)sbuf;
        const int v = bid - (NPREPX + NWDT + NFOLD);
        if (tid == 0) *scnt = 0;
        __syncthreads();
        for (int i = tid; i < BB; i += 256) {
            if (vids[i] == v) {
                int s = atomicAdd(scnt, 1);
                g_bins[v * BB + s] = i;
            }
        }
        __syncthreads();
        if (tid == 0) g_counts[v] = *scnt;
    }
}

// ---------------- main mma.sync kernel: 32-row tiles, full K, 3-stage ring ----------------
extern "C" __global__ void __launch_bounds__(256)
va_main_mma(const float* __restrict__ bd, const float* __restrict__ bc,
            float* __restrict__ out) {
    extern __shared__ char dsm[];
    __shared__ int   sB[MTILE];
    __shared__ float sBd[128];
    __shared__ float sWc2[256];
    __shared__ float sRed[8 * MTILE * 2];

    const int tid  = threadIdx.x;
    const int warp = tid >> 5;     // 0..7 -> 16-col group
    const int lane = tid & 31;

    // ---- derive this CTA's (variety, segment) from counts inline ----
    const int t = blockIdx.x;
    int vv = -1, seg = 0, cnt = 0;
    {
        int nt = 0;
        #pragma unroll
        for (int vi = 0; vi < VV; vi++) {
            int c  = g_counts[vi];
            int tv = (c + MTILE - 1) >> 5;
            if (vv < 0 && t >= nt && t < nt + tv) { vv = vi; seg = t - nt; cnt = c; }
            nt += tv;
        }
    }
    if (vv < 0) return;
    const int row0 = seg * MTILE;

    if (tid < MTILE) {
        int gr = row0 + tid;
        sB[tid] = (gr < cnt) ? g_bins[vv * BB + gr] : -1;
    }
    if (tid < 128) sBd[tid] = bd[vv * AA + tid];
    sWc2[tid] = g_Wc2[vv * AA * LL + tid];
    __syncthreads();

    const uint32_t dynb = smem_to_u32(dsm);
    const __nv_bfloat16* wdtv = g_WdT + (size_t)vv * AA * HH;

    // per-thread cp.async plan: 10 16B loads per chunk (A: 512, B: 2048)
    const __nv_bfloat16* src10[10];
    uint32_t dst10[10];            // offsets relative to stage base
    #pragma unroll
    for (int i = 0; i < 10; i++) {
        int idx = tid + i * 256;
        if (idx < 512) {
            int row = idx >> 4, sg = idx & 15;
            int brow = sB[row];
            if (brow < 0) brow = 0;
            src10[i] = g_xbf16 + (size_t)brow * HH + sg * 8;
            dst10[i] = (uint32_t)(row * STR2 + sg * 16);
        } else {
            int j = idx - 512;
            int row = j >> 4, sg = j & 15;
            src10[i] = wdtv + (size_t)row * HH + sg * 8;
            dst10[i] = (uint32_t)(SA2 + row * STR2 + sg * 16);
        }
    }

    // ldmatrix offsets
    uint32_t aOff[2];
    #pragma unroll
    for (int mf = 0; mf < 2; mf++)
        aOff[mf] = (uint32_t)((16 * mf + ((lane >> 3) & 1) * 8 + (lane & 7)) * STR2
                              + (lane >> 4) * 16);
    uint32_t bOff = (uint32_t)(SA2
                               + (16 * warp + (lane >> 4) * 8 + (lane & 7)) * STR2
                               + ((lane >> 3) & 1) * 16);

    float acc[2][2][4];
    #pragma unroll
    for (int mf = 0; mf < 2; mf++)
        #pragma unroll
        for (int nf = 0; nf < 2; nf++)
            #pragma unroll
            for (int e = 0; e < 4; e++) acc[mf][nf][e] = 0.f;

    // ---- prologue: chunks 0,1 -> stages 0,1 ----
    #pragma unroll
    for (int s = 0; s < 2; s++) {
        uint32_t base = dynb + s * STAGE2;
        #pragma unroll
        for (int i = 0; i < 10; i++)
            CP_ASYNC16(base + dst10[i], src10[i] + s * KCH);
        CP_COMMIT();
    }

    // ---- mainloop: 3-stage ring, depth-2 prefetch ----
    int stc = 0, stn = 2;
    for (int c = 0; c < NCHK; c++) {
        if (c + 2 < NCHK) {
            uint32_t base = dynb + stn * STAGE2;
            const int koff = (c + 2) * KCH;
            #pragma unroll
            for (int i = 0; i < 10; i++)
                CP_ASYNC16(base + dst10[i], src10[i] + koff);
            CP_COMMIT();
            CP_WAITN(2);
        } else if (c + 1 < NCHK) {
            CP_WAITN(1);
        } else {
            CP_WAITN(0);
        }
        __syncthreads();

        const uint32_t base = dynb + stc * STAGE2;
        #pragma unroll
        for (int step = 0; step < 8; step++) {
            const uint32_t kb = step * 32;
            uint32_t af[2][4], bf[4];
            ldsm4(af[0], base + aOff[0] + kb);
            ldsm4(af[1], base + aOff[1] + kb);
            ldsm4(bf, base + bOff + kb);
            #pragma unroll
            for (int mf = 0; mf < 2; mf++) {
                mma16816(acc[mf][0], af[mf], &bf[0]);
                mma16816(acc[mf][1], af[mf], &bf[2]);
            }
        }
        __syncthreads();

        stc = (stc == 2) ? 0 : stc + 1;
        stn = (stn == 2) ? 0 : stn + 1;
    }

    // ---- epilogue: gelu + folded head (all in-CTA) ----
    float rp[2][2][2];   // [mf][hh][l]
    #pragma unroll
    for (int mf = 0; mf < 2; mf++)
        #pragma unroll
        for (int hh = 0; hh < 2; hh++) { rp[mf][hh][0] = 0.f; rp[mf][hh][1] = 0.f; }

    #pragma unroll
    for (int mf = 0; mf < 2; mf++)
        #pragma unroll
        for (int nf = 0; nf < 2; nf++) {
            int col0 = 16 * warp + 8 * nf + 2 * (lane & 3);
            #pragma unroll
            for (int e = 0; e < 4; e++) {
                int col = col0 + (e & 1);
                int hh  = e >> 1;
                float h = gelu_fast(acc[mf][nf][e] + sBd[col]);
                rp[mf][hh][0] = fmaf(h, sWc2[col * 2 + 0], rp[mf][hh][0]);
                rp[mf][hh][1] = fmaf(h, sWc2[col * 2 + 1], rp[mf][hh][1]);
            }
        }

    #pragma unroll
    for (int mf = 0; mf < 2; mf++)
        #pragma unroll
        for (int hh = 0; hh < 2; hh++)
            #pragma unroll
            for (int l = 0; l < 2; l++) {
                float s = rp[mf][hh][l];
                s += __shfl_xor_sync(0xFFFFFFFFu, s, 1);
                s += __shfl_xor_sync(0xFFFFFFFFu, s, 2);
                rp[mf][hh][l] = s;
            }

    if ((lane & 3) == 0) {
        int rbase = lane >> 2;
        #pragma unroll
        for (int mf = 0; mf < 2; mf++)
            #pragma unroll
            for (int hh = 0; hh < 2; hh++) {
                int row = 16 * mf + 8 * hh + rbase;
                sRed[(warp * MTILE + row) * 2 + 0] = rp[mf][hh][0];
                sRed[(warp * MTILE + row) * 2 + 1] = rp[mf][hh][1];
            }
    }
    __syncthreads();

    if (tid < MTILE * LL) {
        int row = tid >> 1;
        int l   = tid & 1;
        int b   = sB[row];
        if (b >= 0) {
            float s = g_xc[b * 2 + l] + g_buc[vv * 2 + l] + __ldg(bc + l);
            #pragma unroll
            for (int w = 0; w < 8; w++)
                s += sRed[(w * MTILE + row) * 2 + l];
            out[b * 2 + l] = s;
        }
    }
}

extern "C" void kernel_launch(void* const* d_in, const int* in_sizes, int n_in,
                              void* d_out, int out_size) {
    const float* lh   = (const float*)d_in[0];
    const int*   vids = (const int*)d_in[2];
    const float* Wd   = (const float*)d_in[3];
    const float* bd   = (const float*)d_in[4];
    const float* Wu   = (const float*)d_in[5];
    const float* bu   = (const float*)d_in[6];
    const float* Wc   = (const float*)d_in[7];
    const float* bc   = (const float*)d_in[8];
    float* out = (float*)d_out;

    cudaFuncSetAttribute(va_main_mma, cudaFuncAttributeMaxDynamicSharedMemorySize, DYN_SMEM);

    va_prep<<<NPREP, 256>>>(lh, Wc, Wd, Wu, bu, vids);
    va_main_mma<<<NTILES_MAX, 256, DYN_SMEM>>>(bd, bc, out);
}